// round 2
// baseline (speedup 1.0000x reference)
#include <cuda_runtime.h>

// Problem constants
#define BB 16
#define SS 1024
#define DD 1024
#define HH 16
#define HD 64

// Scratch for projected q, k (128 MB total, static device arrays — no allocs)
__device__ float g_q[BB * SS * DD];
__device__ float g_k[BB * SS * DD];

// ---------------------------------------------------------------------------
// Kernel 1: C[M=16384, N=2048] = X[M,1024] @ W[N,1024]^T + bias
// Split column-wise into g_q (n<1024) and g_k (n>=1024).
// 128x128x16 tile, 256 threads, 8x8 per-thread microtile.
// ---------------------------------------------------------------------------
__global__ __launch_bounds__(256) void qk_gemm(const float* __restrict__ X,
                                               const float* __restrict__ W,
                                               const float* __restrict__ bias) {
    const int K = 1024;
    __shared__ float As[16][132];  // [k][m], padded
    __shared__ float Bs[16][132];  // [k][n], padded

    int tid = threadIdx.x;
    int m0 = blockIdx.y * 128;
    int n0 = blockIdx.x * 128;
    int tr = tid / 16;          // 0..15  (row group of 8)
    int tc = tid % 16;          // 0..15  (col group of 8)
    int lrow = tid >> 2;        // 0..63  loader row
    int lcol = (tid & 3) * 4;   // 0,4,8,12 loader k-col

    float acc[8][8];
#pragma unroll
    for (int i = 0; i < 8; i++)
#pragma unroll
        for (int j = 0; j < 8; j++) acc[i][j] = 0.0f;

    for (int kt = 0; kt < K; kt += 16) {
#pragma unroll
        for (int r = 0; r < 2; r++) {
            int arow = m0 + lrow + r * 64;
            float4 a = *(const float4*)&X[arow * K + kt + lcol];
            As[lcol + 0][lrow + r * 64] = a.x;
            As[lcol + 1][lrow + r * 64] = a.y;
            As[lcol + 2][lrow + r * 64] = a.z;
            As[lcol + 3][lrow + r * 64] = a.w;
            int brow = n0 + lrow + r * 64;
            float4 b = *(const float4*)&W[brow * K + kt + lcol];
            Bs[lcol + 0][lrow + r * 64] = b.x;
            Bs[lcol + 1][lrow + r * 64] = b.y;
            Bs[lcol + 2][lrow + r * 64] = b.z;
            Bs[lcol + 3][lrow + r * 64] = b.w;
        }
        __syncthreads();

#pragma unroll
        for (int kk = 0; kk < 16; kk++) {
            float a[8], b[8];
            *(float4*)&a[0] = *(const float4*)&As[kk][tr * 8];
            *(float4*)&a[4] = *(const float4*)&As[kk][tr * 8 + 4];
            *(float4*)&b[0] = *(const float4*)&Bs[kk][tc * 8];
            *(float4*)&b[4] = *(const float4*)&Bs[kk][tc * 8 + 4];
#pragma unroll
            for (int i = 0; i < 8; i++)
#pragma unroll
                for (int j = 0; j < 8; j++) acc[i][j] += a[i] * b[j];
        }
        __syncthreads();
    }

    // Epilogue: bias add + split to g_q / g_k
    float bv[8];
#pragma unroll
    for (int j = 0; j < 8; j++) bv[j] = bias[n0 + tc * 8 + j];

    float* dst = (n0 < 1024) ? g_q : g_k;
    int nb = (n0 < 1024) ? n0 : (n0 - 1024);

#pragma unroll
    for (int i = 0; i < 8; i++) {
        int row = m0 + tr * 8 + i;
        float4 v0 = make_float4(acc[i][0] + bv[0], acc[i][1] + bv[1],
                                acc[i][2] + bv[2], acc[i][3] + bv[3]);
        float4 v1 = make_float4(acc[i][4] + bv[4], acc[i][5] + bv[5],
                                acc[i][6] + bv[6], acc[i][7] + bv[7]);
        *(float4*)&dst[row * 1024 + nb + tc * 8] = v0;
        *(float4*)&dst[row * 1024 + nb + tc * 8 + 4] = v1;
    }
}

// ---------------------------------------------------------------------------
// Kernel 2: flash attention. One CTA per (q-block of 64 rows, head, batch).
// BM=64 q rows, BN=32 keys per iter, HD=64. 256 threads as 16x16:
//   thread (ty,tx): S rows ty*4..+3, S cols tx*2..+1, O cols tx*4..+3.
// Online softmax; P staged through smem for the PV contraction.
// ---------------------------------------------------------------------------
__global__ __launch_bounds__(256) void attn(const float* __restrict__ X,
                                            float* __restrict__ Out) {
    __shared__ float Qs[64][65];   // [row][dim], pad 65 (conflict-free scalar)
    __shared__ float Ks[32][65];   // [key][dim], pad 65
    __shared__ float Vs[32][64];   // [key][dim], float4-aligned reads
    __shared__ float Ps[64][34];   // [row][key], pad 34 (even, float2-aligned)

    int tid = threadIdx.x;
    int ty = tid / 16;
    int tx = tid % 16;
    int qb = blockIdx.x;
    int h = blockIdx.y;
    int b = blockIdx.z;

    const float* qbase = g_q + (b * SS) * DD + h * HD;
    const float* kbase = g_k + (b * SS) * DD + h * HD;
    const float* vbase = X + (b * SS) * DD + h * HD;

    // Load Q tile (64x64) scaled by 1/sqrt(HD) = 0.125
    {
        int r = tid / 16;
        int c4 = (tid % 16) * 4;
#pragma unroll
        for (int it = 0; it < 4; it++) {
            int row = it * 16 + r;
            float4 v = *(const float4*)&qbase[(qb * 64 + row) * DD + c4];
            Qs[row][c4 + 0] = v.x * 0.125f;
            Qs[row][c4 + 1] = v.y * 0.125f;
            Qs[row][c4 + 2] = v.z * 0.125f;
            Qs[row][c4 + 3] = v.w * 0.125f;
        }
    }

    float o[4][4];
#pragma unroll
    for (int i = 0; i < 4; i++)
#pragma unroll
        for (int j = 0; j < 4; j++) o[i][j] = 0.0f;
    float mrow[4] = {-1e30f, -1e30f, -1e30f, -1e30f};
    float lrow[4] = {0.0f, 0.0f, 0.0f, 0.0f};

    for (int kb = 0; kb < SS / 32; kb++) {
        __syncthreads();  // prior iter's reads of Ks/Vs/Ps done
        // Load K,V tile (32 keys x 64 dims)
        {
            int r = tid / 16;
            int c4 = (tid % 16) * 4;
#pragma unroll
            for (int it = 0; it < 2; it++) {
                int key = it * 16 + r;
                int gkey = kb * 32 + key;
                float4 kv = *(const float4*)&kbase[gkey * DD + c4];
                Ks[key][c4 + 0] = kv.x;
                Ks[key][c4 + 1] = kv.y;
                Ks[key][c4 + 2] = kv.z;
                Ks[key][c4 + 3] = kv.w;
                float4 vv = *(const float4*)&vbase[gkey * DD + c4];
                *(float4*)&Vs[key][c4] = vv;
            }
        }
        __syncthreads();

        // S = (Q/8) @ K^T  -> s[4][2]
        float s[4][2];
#pragma unroll
        for (int i = 0; i < 4; i++) { s[i][0] = 0.0f; s[i][1] = 0.0f; }
#pragma unroll
        for (int kk = 0; kk < 64; kk++) {
            float k0 = Ks[tx * 2 + 0][kk];
            float k1 = Ks[tx * 2 + 1][kk];
#pragma unroll
            for (int i = 0; i < 4; i++) {
                float q = Qs[ty * 4 + i][kk];
                s[i][0] += q * k0;
                s[i][1] += q * k1;
            }
        }

        // Online softmax update (row groups of 16 lanes share a q-row)
#pragma unroll
        for (int i = 0; i < 4; i++) {
            float mx = fmaxf(s[i][0], s[i][1]);
#pragma unroll
            for (int off = 8; off >= 1; off >>= 1)
                mx = fmaxf(mx, __shfl_xor_sync(0xffffffffu, mx, off, 16));
            float mnew = fmaxf(mrow[i], mx);
            float corr = __expf(mrow[i] - mnew);
            mrow[i] = mnew;
            float p0 = __expf(s[i][0] - mnew);
            float p1 = __expf(s[i][1] - mnew);
            s[i][0] = p0;
            s[i][1] = p1;
            float sum = p0 + p1;
#pragma unroll
            for (int off = 8; off >= 1; off >>= 1)
                sum += __shfl_xor_sync(0xffffffffu, sum, off, 16);
            lrow[i] = lrow[i] * corr + sum;
#pragma unroll
            for (int j = 0; j < 4; j++) o[i][j] *= corr;
        }

        // Stage P to smem
#pragma unroll
        for (int i = 0; i < 4; i++)
            *(float2*)&Ps[ty * 4 + i][tx * 2] = make_float2(s[i][0], s[i][1]);
        __syncthreads();

        // O += P @ V
#pragma unroll
        for (int kk = 0; kk < 32; kk++) {
            float4 v = *(const float4*)&Vs[kk][tx * 4];
#pragma unroll
            for (int i = 0; i < 4; i++) {
                float p = Ps[ty * 4 + i][kk];
                o[i][0] += p * v.x;
                o[i][1] += p * v.y;
                o[i][2] += p * v.z;
                o[i][3] += p * v.w;
            }
        }
    }

    // Normalize + write out[b, s, h*64 + c]
#pragma unroll
    for (int i = 0; i < 4; i++) {
        float inv = 1.0f / lrow[i];
        int srow = qb * 64 + ty * 4 + i;
        float4 v = make_float4(o[i][0] * inv, o[i][1] * inv,
                               o[i][2] * inv, o[i][3] * inv);
        *(float4*)&Out[(b * SS + srow) * DD + h * HD + tx * 4] = v;
    }
}

extern "C" void kernel_launch(void* const* d_in, const int* in_sizes, int n_in,
                              void* d_out, int out_size) {
    const float* X = (const float*)d_in[0];     // [16,1024,1024]
    const float* W = (const float*)d_in[1];     // [2048,1024]
    const float* bias = (const float*)d_in[2];  // [2048]
    float* Out = (float*)d_out;                 // [16,1024,1024]

    dim3 g1(2048 / 128, 16384 / 128);  // (16, 128)
    qk_gemm<<<g1, 256>>>(X, W, bias);

    dim3 g2(SS / 64, HH, BB);  // (16, 16, 16)
    attn<<<g2, 256>>>(X, Out);
}

// round 4
// speedup vs baseline: 1.2532x; 1.2532x over previous
#include <cuda_runtime.h>
#include <cuda_bf16.h>
#include <cstdint>

// Problem constants
#define BB 16
#define SS 1024
#define DD 1024
#define HH 16
#define HD 64
#define K3 3072   // split-K: [hi|hi|lo] x [hi|lo|hi]

// Scratch (static __device__ arrays -- no allocations)
__device__ float g_q[BB * SS * DD];
__device__ float g_k[BB * SS * DD];
__device__ __nv_bfloat16 g_xs[BB * SS * K3];   // ~100 MB
__device__ __nv_bfloat16 g_ws[2048 * K3];      // 12 MB

// ---------------------------------------------------------------------------
// PTX helpers (portable: sm_80+ PTX, valid on compute_103)
// ---------------------------------------------------------------------------
__device__ __forceinline__ uint32_t smem_u32(const void* p) {
    uint32_t a;
    asm("{ .reg .u64 t; cvta.to.shared.u64 t, %1; cvt.u32.u64 %0, t; }"
        : "=r"(a) : "l"(p));
    return a;
}
__device__ __forceinline__ void cp16(uint32_t saddr, const void* g) {
    asm volatile("cp.async.cg.shared.global [%0], [%1], 16;" :: "r"(saddr), "l"(g));
}
__device__ __forceinline__ void ldsm_x4(uint32_t& r0, uint32_t& r1, uint32_t& r2,
                                        uint32_t& r3, uint32_t addr) {
    asm volatile("ldmatrix.sync.aligned.m8n8.x4.shared.b16 {%0,%1,%2,%3}, [%4];"
                 : "=r"(r0), "=r"(r1), "=r"(r2), "=r"(r3) : "r"(addr));
}
__device__ __forceinline__ void mma_bf16(float* c, uint32_t a0, uint32_t a1,
                                         uint32_t a2, uint32_t a3,
                                         uint32_t b0, uint32_t b1) {
    asm volatile(
        "mma.sync.aligned.m16n8k16.row.col.f32.bf16.bf16.f32 "
        "{%0,%1,%2,%3}, {%4,%5,%6,%7}, {%8,%9}, {%0,%1,%2,%3};"
        : "+f"(c[0]), "+f"(c[1]), "+f"(c[2]), "+f"(c[3])
        : "r"(a0), "r"(a1), "r"(a2), "r"(a3), "r"(b0), "r"(b1));
}
__device__ __forceinline__ uint32_t sw128(uint32_t byte) {
    return byte ^ ((byte >> 3) & 0x70);
}

// ---------------------------------------------------------------------------
// bf16 split conversion: x -> hi, lo = bf16(x - hi)
// g_xs row = [hi | hi | lo],  g_ws row = [hi | lo | hi]
// => bf16 dot over K'=3072 = hi*hi + hi*lo + lo*hi  (drops only lo*lo)
// ---------------------------------------------------------------------------
__global__ void conv_x(const float* __restrict__ X) {
    int i = blockIdx.x * blockDim.x + threadIdx.x;
    if (i >= BB * SS * DD) return;
    int r = i >> 10, c = i & 1023;
    float x = X[i];
    __nv_bfloat16 hi = __float2bfloat16(x);
    __nv_bfloat16 lo = __float2bfloat16(x - __bfloat162float(hi));
    size_t base = (size_t)r * K3;
    g_xs[base + c] = hi;
    g_xs[base + 1024 + c] = hi;
    g_xs[base + 2048 + c] = lo;
}
__global__ void conv_w(const float* __restrict__ W) {
    int i = blockIdx.x * blockDim.x + threadIdx.x;
    if (i >= 2048 * 1024) return;
    int r = i >> 10, c = i & 1023;
    float w = W[i];
    __nv_bfloat16 hi = __float2bfloat16(w);
    __nv_bfloat16 lo = __float2bfloat16(w - __bfloat162float(hi));
    size_t base = (size_t)r * K3;
    g_ws[base + c] = hi;
    g_ws[base + 1024 + c] = lo;
    g_ws[base + 2048 + c] = hi;
}

// ---------------------------------------------------------------------------
// HMMA bf16 GEMM: C[16384, 2048] = Xs @ Ws^T (K'=3072) + bias -> g_q / g_k
// CTA 128x128, BK=64, 3-stage cp.async, 8 warps (2x4), warp tile 64x32,
// mma.m16n8k16 with ldmatrix.x4 from SW128 smem.
// ---------------------------------------------------------------------------
#define BK 64
#define NSTAGE 3
#define STAGE_BYTES 32768               // A 16KB + B 16KB
#define GEMM_SMEM (NSTAGE * STAGE_BYTES)

__global__ __launch_bounds__(256) void gemm_hmma(const float* __restrict__ bias) {
    extern __shared__ char smem[];
    const uint32_t sbase = smem_u32(smem);
    const int tid = threadIdx.x;
    const int lane = tid & 31;
    const int wid = tid >> 5;
    const int warp_m = wid >> 2;        // 0..1
    const int warp_n = wid & 3;         // 0..3
    const int n0 = blockIdx.x * 128;
    const int m0 = blockIdx.y * 128;

    const __nv_bfloat16* gA = g_xs + (size_t)m0 * K3;
    const __nv_bfloat16* gB = g_ws + (size_t)n0 * K3;

    // Per-stage loader: A/B tiles are 128 rows x 64 bf16 (128 B rows, SW128).
    auto load_stage = [&](int kc, int s) {
        uint32_t sA = sbase + s * STAGE_BYTES;
        uint32_t sB = sA + 16384;
        const __nv_bfloat16* a = gA + kc * BK;
        const __nv_bfloat16* b = gB + kc * BK;
#pragma unroll
        for (int i = 0; i < 4; i++) {
            int idx = tid + i * 256;            // 0..1023
            int r = idx >> 3, q = idx & 7;
            uint32_t sw = sw128(r * 128 + q * 16);
            cp16(sA + sw, a + (size_t)r * K3 + q * 8);
            cp16(sB + sw, b + (size_t)r * K3 + q * 8);
        }
        asm volatile("cp.async.commit_group;" ::: "memory");
    };

    float acc[4][4][4];
#pragma unroll
    for (int mi = 0; mi < 4; mi++)
#pragma unroll
        for (int nt = 0; nt < 4; nt++)
#pragma unroll
            for (int k = 0; k < 4; k++) acc[mi][nt][k] = 0.0f;

    const int NK = K3 / BK;  // 48
    load_stage(0, 0);
    load_stage(1, 1);

    for (int kc = 0; kc < NK; kc++) {
        int s = kc % NSTAGE;
        if (kc + 1 < NK) asm volatile("cp.async.wait_group 1;" ::: "memory");
        else             asm volatile("cp.async.wait_group 0;" ::: "memory");
        __syncthreads();
        if (kc + 2 < NK) load_stage(kc + 2, (kc + 2) % NSTAGE);

        uint32_t sA = sbase + s * STAGE_BYTES;
        uint32_t sB = sA + 16384;

#pragma unroll
        for (int kk = 0; kk < BK / 16; kk++) {   // 4 k-steps of 16
            uint32_t a[4][4], bfr[2][4];
            int colb = kk * 32 + ((lane >> 4) << 4);   // byte col within 128B row
#pragma unroll
            for (int mi = 0; mi < 4; mi++) {
                int row = warp_m * 64 + mi * 16 + (lane & 15);
                uint32_t addr = sA + sw128(row * 128 + colb);
                ldsm_x4(a[mi][0], a[mi][1], a[mi][2], a[mi][3], addr);
            }
#pragma unroll
            for (int p = 0; p < 2; p++) {
                int row = warp_n * 32 + p * 16 + (lane & 15);
                uint32_t addr = sB + sw128(row * 128 + colb);
                ldsm_x4(bfr[p][0], bfr[p][1], bfr[p][2], bfr[p][3], addr);
            }
            // b-tiles: nt = p*2 + {0,1}; nt even -> regs {r0,r2}, odd -> {r1,r3}
#pragma unroll
            for (int mi = 0; mi < 4; mi++) {
#pragma unroll
                for (int p = 0; p < 2; p++) {
                    mma_bf16(acc[mi][p * 2 + 0], a[mi][0], a[mi][1], a[mi][2], a[mi][3],
                             bfr[p][0], bfr[p][2]);
                    mma_bf16(acc[mi][p * 2 + 1], a[mi][0], a[mi][1], a[mi][2], a[mi][3],
                             bfr[p][1], bfr[p][3]);
                }
            }
        }
        __syncthreads();
    }

    // Epilogue: bias + split to g_q / g_k
    float* dst;
    int nb;
    if (n0 < 1024) { dst = g_q; nb = n0; }
    else           { dst = g_k; nb = n0 - 1024; }

#pragma unroll
    for (int mi = 0; mi < 4; mi++) {
        int r0 = m0 + warp_m * 64 + mi * 16 + (lane >> 2);
#pragma unroll
        for (int nt = 0; nt < 4; nt++) {
            int c = warp_n * 32 + nt * 8 + (lane & 3) * 2;
            float b0 = __ldg(&bias[n0 + c]);
            float b1 = __ldg(&bias[n0 + c + 1]);
            float2 v0 = make_float2(acc[mi][nt][0] + b0, acc[mi][nt][1] + b1);
            float2 v1 = make_float2(acc[mi][nt][2] + b0, acc[mi][nt][3] + b1);
            *(float2*)&dst[(size_t)r0 * 1024 + nb + c] = v0;
            *(float2*)&dst[(size_t)(r0 + 8) * 1024 + nb + c] = v1;
        }
    }
}

// ---------------------------------------------------------------------------
// Kernel 2: flash attention (unchanged from passing round-2 kernel)
// ---------------------------------------------------------------------------
__global__ __launch_bounds__(256) void attn(const float* __restrict__ X,
                                            float* __restrict__ Out) {
    __shared__ float Qs[64][65];
    __shared__ float Ks[32][65];
    __shared__ float Vs[32][64];
    __shared__ float Ps[64][34];

    int tid = threadIdx.x;
    int ty = tid / 16;
    int tx = tid % 16;
    int qb = blockIdx.x;
    int h = blockIdx.y;
    int b = blockIdx.z;

    const float* qbase = g_q + (b * SS) * DD + h * HD;
    const float* kbase = g_k + (b * SS) * DD + h * HD;
    const float* vbase = X + (b * SS) * DD + h * HD;

    {
        int r = tid / 16;
        int c4 = (tid % 16) * 4;
#pragma unroll
        for (int it = 0; it < 4; it++) {
            int row = it * 16 + r;
            float4 v = *(const float4*)&qbase[(qb * 64 + row) * DD + c4];
            Qs[row][c4 + 0] = v.x * 0.125f;
            Qs[row][c4 + 1] = v.y * 0.125f;
            Qs[row][c4 + 2] = v.z * 0.125f;
            Qs[row][c4 + 3] = v.w * 0.125f;
        }
    }

    float o[4][4];
#pragma unroll
    for (int i = 0; i < 4; i++)
#pragma unroll
        for (int j = 0; j < 4; j++) o[i][j] = 0.0f;
    float mrow[4] = {-1e30f, -1e30f, -1e30f, -1e30f};
    float lrow[4] = {0.0f, 0.0f, 0.0f, 0.0f};

    for (int kb = 0; kb < SS / 32; kb++) {
        __syncthreads();
        {
            int r = tid / 16;
            int c4 = (tid % 16) * 4;
#pragma unroll
            for (int it = 0; it < 2; it++) {
                int key = it * 16 + r;
                int gkey = kb * 32 + key;
                float4 kv = *(const float4*)&kbase[gkey * DD + c4];
                Ks[key][c4 + 0] = kv.x;
                Ks[key][c4 + 1] = kv.y;
                Ks[key][c4 + 2] = kv.z;
                Ks[key][c4 + 3] = kv.w;
                float4 vv = *(const float4*)&vbase[gkey * DD + c4];
                *(float4*)&Vs[key][c4] = vv;
            }
        }
        __syncthreads();

        float s[4][2];
#pragma unroll
        for (int i = 0; i < 4; i++) { s[i][0] = 0.0f; s[i][1] = 0.0f; }
#pragma unroll
        for (int kk = 0; kk < 64; kk++) {
            float k0 = Ks[tx * 2 + 0][kk];
            float k1 = Ks[tx * 2 + 1][kk];
#pragma unroll
            for (int i = 0; i < 4; i++) {
                float q = Qs[ty * 4 + i][kk];
                s[i][0] += q * k0;
                s[i][1] += q * k1;
            }
        }

#pragma unroll
        for (int i = 0; i < 4; i++) {
            float mx = fmaxf(s[i][0], s[i][1]);
#pragma unroll
            for (int off = 8; off >= 1; off >>= 1)
                mx = fmaxf(mx, __shfl_xor_sync(0xffffffffu, mx, off, 16));
            float mnew = fmaxf(mrow[i], mx);
            float corr = __expf(mrow[i] - mnew);
            mrow[i] = mnew;
            float p0 = __expf(s[i][0] - mnew);
            float p1 = __expf(s[i][1] - mnew);
            s[i][0] = p0;
            s[i][1] = p1;
            float sum = p0 + p1;
#pragma unroll
            for (int off = 8; off >= 1; off >>= 1)
                sum += __shfl_xor_sync(0xffffffffu, sum, off, 16);
            lrow[i] = lrow[i] * corr + sum;
#pragma unroll
            for (int j = 0; j < 4; j++) o[i][j] *= corr;
        }

#pragma unroll
        for (int i = 0; i < 4; i++)
            *(float2*)&Ps[ty * 4 + i][tx * 2] = make_float2(s[i][0], s[i][1]);
        __syncthreads();

#pragma unroll
        for (int kk = 0; kk < 32; kk++) {
            float4 v = *(const float4*)&Vs[kk][tx * 4];
#pragma unroll
            for (int i = 0; i < 4; i++) {
                float p = Ps[ty * 4 + i][kk];
                o[i][0] += p * v.x;
                o[i][1] += p * v.y;
                o[i][2] += p * v.z;
                o[i][3] += p * v.w;
            }
        }
    }

#pragma unroll
    for (int i = 0; i < 4; i++) {
        float inv = 1.0f / lrow[i];
        int srow = qb * 64 + ty * 4 + i;
        float4 v = make_float4(o[i][0] * inv, o[i][1] * inv,
                               o[i][2] * inv, o[i][3] * inv);
        *(float4*)&Out[(b * SS + srow) * DD + h * HD + tx * 4] = v;
    }
}

extern "C" void kernel_launch(void* const* d_in, const int* in_sizes, int n_in,
                              void* d_out, int out_size) {
    const float* X = (const float*)d_in[0];     // [16,1024,1024]
    const float* W = (const float*)d_in[1];     // [2048,1024]
    const float* bias = (const float*)d_in[2];  // [2048]
    float* Out = (float*)d_out;                 // [16,1024,1024]

    cudaFuncSetAttribute(gemm_hmma, cudaFuncAttributeMaxDynamicSharedMemorySize,
                         GEMM_SMEM);

    conv_x<<<(BB * SS * DD + 255) / 256, 256>>>(X);
    conv_w<<<(2048 * 1024 + 255) / 256, 256>>>(W);
    gemm_hmma<<<dim3(16, 128), 256, GEMM_SMEM>>>(bias);

    dim3 g2(SS / 64, HH, BB);
    attn<<<g2, 256>>>(X, Out);
}

// round 5
// speedup vs baseline: 2.9717x; 2.3713x over previous
#include <cuda_runtime.h>
#include <cuda_bf16.h>
#include <cstdint>

// Problem constants
#define BB 16
#define SS 1024
#define DD 1024
#define HH 16
#define HD 64
#define K3 3072   // gemm split-K: [hi|hi|lo] x [hi|lo|hi]

// Scratch (static __device__ arrays -- no allocations)
__device__ __nv_bfloat16 g_xs[BB * SS * K3];        // ~100 MB
__device__ __nv_bfloat16 g_ws[2048 * K3];           // 12 MB
// Split Q/K, head-major: [(b*16+h)*1024 + s][128] = [qhi(64) | qlo(64)]
__device__ __nv_bfloat16 g_qs[BB * HH * SS * 128];  // 64 MB
__device__ __nv_bfloat16 g_ks[BB * HH * SS * 128];  // 64 MB
// V transposed split: [(bh*2 + hl)*64 + dim][1024 keys]
__device__ __nv_bfloat16 g_vt[BB * HH * 2 * 64 * SS]; // 64 MB

// ---------------------------------------------------------------------------
// PTX helpers (sm_80-level PTX; valid on compute_103)
// ---------------------------------------------------------------------------
__device__ __forceinline__ uint32_t smem_u32(const void* p) {
    uint32_t a;
    asm("{ .reg .u64 t; cvta.to.shared.u64 t, %1; cvt.u32.u64 %0, t; }"
        : "=r"(a) : "l"(p));
    return a;
}
__device__ __forceinline__ void cp16(uint32_t saddr, const void* g) {
    asm volatile("cp.async.cg.shared.global [%0], [%1], 16;" :: "r"(saddr), "l"(g));
}
__device__ __forceinline__ void ldsm_x4(uint32_t& r0, uint32_t& r1, uint32_t& r2,
                                        uint32_t& r3, uint32_t addr) {
    asm volatile("ldmatrix.sync.aligned.m8n8.x4.shared.b16 {%0,%1,%2,%3}, [%4];"
                 : "=r"(r0), "=r"(r1), "=r"(r2), "=r"(r3) : "r"(addr));
}
__device__ __forceinline__ void mma_bf16(float* c, uint32_t a0, uint32_t a1,
                                         uint32_t a2, uint32_t a3,
                                         uint32_t b0, uint32_t b1) {
    asm volatile(
        "mma.sync.aligned.m16n8k16.row.col.f32.bf16.bf16.f32 "
        "{%0,%1,%2,%3}, {%4,%5,%6,%7}, {%8,%9}, {%0,%1,%2,%3};"
        : "+f"(c[0]), "+f"(c[1]), "+f"(c[2]), "+f"(c[3])
        : "r"(a0), "r"(a1), "r"(a2), "r"(a3), "r"(b0), "r"(b1));
}
__device__ __forceinline__ uint32_t sw128(uint32_t byte) {
    return byte ^ ((byte >> 3) & 0x70);
}
__device__ __forceinline__ float ex2f(float x) {
    float y;
    asm("ex2.approx.ftz.f32 %0, %1;" : "=f"(y) : "f"(x));
    return y;
}
__device__ __forceinline__ uint32_t pack_bf2(float a, float b) {
    __nv_bfloat162 h;
    h.x = __float2bfloat16(a);
    h.y = __float2bfloat16(b);
    return *reinterpret_cast<uint32_t*>(&h);
}

// ---------------------------------------------------------------------------
// bf16 split conversion for the projection GEMM
// ---------------------------------------------------------------------------
__global__ void conv_x(const float* __restrict__ X) {
    int i = blockIdx.x * blockDim.x + threadIdx.x;
    if (i >= BB * SS * DD) return;
    int r = i >> 10, c = i & 1023;
    float x = X[i];
    __nv_bfloat16 hi = __float2bfloat16(x);
    __nv_bfloat16 lo = __float2bfloat16(x - __bfloat162float(hi));
    size_t base = (size_t)r * K3;
    g_xs[base + c] = hi;
    g_xs[base + 1024 + c] = hi;
    g_xs[base + 2048 + c] = lo;
}
__global__ void conv_w(const float* __restrict__ W) {
    int i = blockIdx.x * blockDim.x + threadIdx.x;
    if (i >= 2048 * 1024) return;
    int r = i >> 10, c = i & 1023;
    float w = W[i];
    __nv_bfloat16 hi = __float2bfloat16(w);
    __nv_bfloat16 lo = __float2bfloat16(w - __bfloat162float(hi));
    size_t base = (size_t)r * K3;
    g_ws[base + c] = hi;
    g_ws[base + 1024 + c] = lo;
    g_ws[base + 2048 + c] = hi;
}

// V transpose + split: per (kb, h, b) tile of 64 keys x 64 dims
__global__ __launch_bounds__(256) void conv_vt(const float* __restrict__ X) {
    __shared__ float tile[64][65];
    int kb = blockIdx.x, h = blockIdx.y, b = blockIdx.z;
    int tid = threadIdx.x;
#pragma unroll
    for (int i = 0; i < 4; i++) {
        int row = i * 16 + tid / 16;
        int c4 = (tid % 16) * 4;
        float4 v = *(const float4*)&X[((size_t)b * SS + kb * 64 + row) * DD + h * 64 + c4];
        tile[row][c4 + 0] = v.x;
        tile[row][c4 + 1] = v.y;
        tile[row][c4 + 2] = v.z;
        tile[row][c4 + 3] = v.w;
    }
    __syncthreads();
    int bh = b * HH + h;
#pragma unroll
    for (int i = 0; i < 16; i++) {
        int e = tid + i * 256;
        int dim = e >> 6, key = e & 63;
        float x = tile[key][dim];
        __nv_bfloat16 hi = __float2bfloat16(x);
        __nv_bfloat16 lo = __float2bfloat16(x - __bfloat162float(hi));
        g_vt[((size_t)(bh * 2 + 0) * 64 + dim) * SS + kb * 64 + key] = hi;
        g_vt[((size_t)(bh * 2 + 1) * 64 + dim) * SS + kb * 64 + key] = lo;
    }
}

// ---------------------------------------------------------------------------
// HMMA bf16 GEMM: C[16384, 2048] = Xs @ Ws^T (K'=3072) + bias
// Epilogue emits split bf16 directly to g_qs / g_ks (q pre-scaled by
// 0.125*log2(e) so attention softmax can use exp2).
// ---------------------------------------------------------------------------
#define BK 64
#define NSTAGE 3
#define STAGE_BYTES 32768
#define GEMM_SMEM (NSTAGE * STAGE_BYTES)

__global__ __launch_bounds__(256) void gemm_hmma(const float* __restrict__ bias) {
    extern __shared__ char smem[];
    const uint32_t sbase = smem_u32(smem);
    const int tid = threadIdx.x;
    const int lane = tid & 31;
    const int wid = tid >> 5;
    const int warp_m = wid >> 2;
    const int warp_n = wid & 3;
    const int n0 = blockIdx.x * 128;
    const int m0 = blockIdx.y * 128;

    const __nv_bfloat16* gA = g_xs + (size_t)m0 * K3;
    const __nv_bfloat16* gB = g_ws + (size_t)n0 * K3;

    auto load_stage = [&](int kc, int s) {
        uint32_t sA = sbase + s * STAGE_BYTES;
        uint32_t sB = sA + 16384;
        const __nv_bfloat16* a = gA + kc * BK;
        const __nv_bfloat16* b = gB + kc * BK;
#pragma unroll
        for (int i = 0; i < 4; i++) {
            int idx = tid + i * 256;
            int r = idx >> 3, q = idx & 7;
            uint32_t sw = sw128(r * 128 + q * 16);
            cp16(sA + sw, a + (size_t)r * K3 + q * 8);
            cp16(sB + sw, b + (size_t)r * K3 + q * 8);
        }
        asm volatile("cp.async.commit_group;" ::: "memory");
    };

    float acc[4][4][4];
#pragma unroll
    for (int mi = 0; mi < 4; mi++)
#pragma unroll
        for (int nt = 0; nt < 4; nt++)
#pragma unroll
            for (int k = 0; k < 4; k++) acc[mi][nt][k] = 0.0f;

    const int NK = K3 / BK;
    load_stage(0, 0);
    load_stage(1, 1);

    for (int kc = 0; kc < NK; kc++) {
        int s = kc % NSTAGE;
        if (kc + 1 < NK) asm volatile("cp.async.wait_group 1;" ::: "memory");
        else             asm volatile("cp.async.wait_group 0;" ::: "memory");
        __syncthreads();
        if (kc + 2 < NK) load_stage(kc + 2, (kc + 2) % NSTAGE);

        uint32_t sA = sbase + s * STAGE_BYTES;
        uint32_t sB = sA + 16384;

#pragma unroll
        for (int kk = 0; kk < BK / 16; kk++) {
            uint32_t a[4][4], bfr[2][4];
            int colb = kk * 32 + ((lane >> 4) << 4);
#pragma unroll
            for (int mi = 0; mi < 4; mi++) {
                int row = warp_m * 64 + mi * 16 + (lane & 15);
                ldsm_x4(a[mi][0], a[mi][1], a[mi][2], a[mi][3],
                        sA + sw128(row * 128 + colb));
            }
#pragma unroll
            for (int p = 0; p < 2; p++) {
                int row = warp_n * 32 + p * 16 + (lane & 15);
                ldsm_x4(bfr[p][0], bfr[p][1], bfr[p][2], bfr[p][3],
                        sB + sw128(row * 128 + colb));
            }
#pragma unroll
            for (int mi = 0; mi < 4; mi++) {
#pragma unroll
                for (int p = 0; p < 2; p++) {
                    mma_bf16(acc[mi][p * 2 + 0], a[mi][0], a[mi][1], a[mi][2], a[mi][3],
                             bfr[p][0], bfr[p][2]);
                    mma_bf16(acc[mi][p * 2 + 1], a[mi][0], a[mi][1], a[mi][2], a[mi][3],
                             bfr[p][1], bfr[p][3]);
                }
            }
        }
        __syncthreads();
    }

    // Epilogue: bias, scale (q only), bf16 split, head-major store
    const float QSCALE = 0.18033688011112042f;  // 0.125 * log2(e)
    float scale = (n0 < 1024) ? QSCALE : 1.0f;
    __nv_bfloat16* dst = (n0 < 1024) ? g_qs : g_ks;

#pragma unroll
    for (int mi = 0; mi < 4; mi++) {
#pragma unroll
        for (int nt = 0; nt < 4; nt++) {
            int c = warp_n * 32 + nt * 8 + (lane & 3) * 2;
            int nn = (n0 + c) & 1023;
            int hh_ = nn >> 6, d = nn & 63;
            float b0 = __ldg(&bias[n0 + c]);
            float b1 = __ldg(&bias[n0 + c + 1]);
#pragma unroll
            for (int rr = 0; rr < 2; rr++) {
                int r = m0 + warp_m * 64 + mi * 16 + (lane >> 2) + rr * 8;
                int bb = r >> 10, s2 = r & 1023;
                size_t base = ((size_t)(bb * HH + hh_) * SS + s2) * 128;
                float v0 = (acc[mi][nt][rr * 2 + 0] + b0) * scale;
                float v1 = (acc[mi][nt][rr * 2 + 1] + b1) * scale;
                __nv_bfloat16 h0 = __float2bfloat16(v0);
                __nv_bfloat16 h1 = __float2bfloat16(v1);
                __nv_bfloat162 hh, ll;
                hh.x = h0; hh.y = h1;
                ll.x = __float2bfloat16(v0 - __bfloat162float(h0));
                ll.y = __float2bfloat16(v1 - __bfloat162float(h1));
                *(__nv_bfloat162*)&dst[base + d] = hh;
                *(__nv_bfloat162*)&dst[base + 64 + d] = ll;
            }
        }
    }
}

// ---------------------------------------------------------------------------
// HMMA flash attention. CTA = (qb: 128 rows, h, b). 8 warps x 16 q-rows.
// BN=64 keys/iter, 2-stage cp.async. 3-term split on both QK and PV.
// ---------------------------------------------------------------------------
#define ATT_SMEM (32768 + 2 * 32768)  // Q tiles + 2 stages = 96 KB

__global__ __launch_bounds__(256) void attn_tc(float* __restrict__ Out) {
    extern __shared__ char smem[];
    const uint32_t sb = smem_u32(smem);
    const int tid = threadIdx.x;
    const int lane = tid & 31;
    const int wid = tid >> 5;
    const int qb = blockIdx.x, h = blockIdx.y, b = blockIdx.z;
    const int bh = b * HH + h;

    const uint32_t QHI = sb, QLO = sb + 16384;
    // stage layout: khi(8K) | klo(8K) | vhi(8K) | vlo(8K)
    auto STAGE = [&](int s) { return sb + 32768 + s * 32768; };

    // Load Q tiles (128 rows x [hi64|lo64])
    {
        const __nv_bfloat16* qsrc = g_qs + ((size_t)bh * SS + qb * 128) * 128;
#pragma unroll
        for (int i = 0; i < 4; i++) {
            int e = tid + i * 256;
            int row = e >> 3, q = e & 7;
            uint32_t sw = sw128(row * 128 + q * 16);
            cp16(QHI + sw, qsrc + (size_t)row * 128 + q * 8);
            cp16(QLO + sw, qsrc + (size_t)row * 128 + 64 + q * 8);
        }
        asm volatile("cp.async.commit_group;" ::: "memory");
    }

    auto load_kv = [&](int kb, int s) {
        uint32_t st = STAGE(s);
        const __nv_bfloat16* ks = g_ks + ((size_t)bh * SS + kb * 64) * 128;
        const __nv_bfloat16* vh = g_vt + (size_t)(bh * 2 + 0) * 64 * SS + kb * 64;
        const __nv_bfloat16* vl = g_vt + (size_t)(bh * 2 + 1) * 64 * SS + kb * 64;
#pragma unroll
        for (int i = 0; i < 2; i++) {
            int e = tid + i * 256;
            int row = e >> 3, q = e & 7;
            uint32_t sw = sw128(row * 128 + q * 16);
            cp16(st + sw, ks + (size_t)row * 128 + q * 8);
            cp16(st + 8192 + sw, ks + (size_t)row * 128 + 64 + q * 8);
            cp16(st + 16384 + sw, vh + (size_t)row * SS + q * 8);
            cp16(st + 24576 + sw, vl + (size_t)row * SS + q * 8);
        }
        asm volatile("cp.async.commit_group;" ::: "memory");
    };

    load_kv(0, 0);
    load_kv(1, 1);

    float oacc[8][4];
#pragma unroll
    for (int t = 0; t < 8; t++)
#pragma unroll
        for (int k = 0; k < 4; k++) oacc[t][k] = 0.0f;
    float m0 = -1e30f, m1 = -1e30f, l0 = 0.0f, l1 = 0.0f;

    const int NIT = SS / 64;  // 16
    for (int kb = 0; kb < NIT; kb++) {
        int s = kb & 1;
        if (kb + 1 < NIT) asm volatile("cp.async.wait_group 1;" ::: "memory");
        else              asm volatile("cp.async.wait_group 0;" ::: "memory");
        __syncthreads();

        uint32_t st = STAGE(s);
        // ---- S = QK^T (3 split passes) ----
        float sacc[8][4];
#pragma unroll
        for (int t = 0; t < 8; t++)
#pragma unroll
            for (int k = 0; k < 4; k++) sacc[t][k] = 0.0f;

#pragma unroll
        for (int pass = 0; pass < 3; pass++) {
            uint32_t aT = (pass == 2) ? QLO : QHI;
            uint32_t bT = (pass == 1) ? (st + 8192) : st;
#pragma unroll
            for (int kk = 0; kk < 4; kk++) {
                int colb = kk * 32 + ((lane >> 4) << 4);
                uint32_t a0, a1, a2, a3;
                {
                    int row = wid * 16 + (lane & 15);
                    ldsm_x4(a0, a1, a2, a3, aT + sw128(row * 128 + colb));
                }
#pragma unroll
                for (int p = 0; p < 4; p++) {
                    uint32_t r0, r1, r2, r3;
                    int row = p * 16 + (lane & 15);
                    ldsm_x4(r0, r1, r2, r3, bT + sw128(row * 128 + colb));
                    mma_bf16(sacc[2 * p + 0], a0, a1, a2, a3, r0, r2);
                    mma_bf16(sacc[2 * p + 1], a0, a1, a2, a3, r1, r3);
                }
            }
        }

        // ---- online softmax (scores already in log2 domain) ----
        float mx0 = -1e30f, mx1 = -1e30f;
#pragma unroll
        for (int t = 0; t < 8; t++) {
            mx0 = fmaxf(mx0, fmaxf(sacc[t][0], sacc[t][1]));
            mx1 = fmaxf(mx1, fmaxf(sacc[t][2], sacc[t][3]));
        }
        mx0 = fmaxf(mx0, __shfl_xor_sync(0xffffffffu, mx0, 1));
        mx0 = fmaxf(mx0, __shfl_xor_sync(0xffffffffu, mx0, 2));
        mx1 = fmaxf(mx1, __shfl_xor_sync(0xffffffffu, mx1, 1));
        mx1 = fmaxf(mx1, __shfl_xor_sync(0xffffffffu, mx1, 2));
        float mn0 = fmaxf(m0, mx0), mn1 = fmaxf(m1, mx1);
        float c0 = ex2f(m0 - mn0), c1 = ex2f(m1 - mn1);
        m0 = mn0; m1 = mn1;

        uint32_t pa_hi[4][4], pa_lo[4][4];
        float sum0 = 0.0f, sum1 = 0.0f;
#pragma unroll
        for (int t = 0; t < 8; t++) {
            float p0 = ex2f(sacc[t][0] - mn0);
            float p1 = ex2f(sacc[t][1] - mn0);
            float p2 = ex2f(sacc[t][2] - mn1);
            float p3 = ex2f(sacc[t][3] - mn1);
            sum0 += p0 + p1;
            sum1 += p2 + p3;
            __nv_bfloat16 h0 = __float2bfloat16(p0), h1 = __float2bfloat16(p1);
            __nv_bfloat16 h2 = __float2bfloat16(p2), h3 = __float2bfloat16(p3);
            int kk = t >> 1, o = (t & 1) * 2;
            {
                __nv_bfloat162 u; u.x = h0; u.y = h1;
                pa_hi[kk][o + 0] = *reinterpret_cast<uint32_t*>(&u);
            }
            {
                __nv_bfloat162 u; u.x = h2; u.y = h3;
                pa_hi[kk][o + 1] = *reinterpret_cast<uint32_t*>(&u);
            }
            pa_lo[kk][o + 0] = pack_bf2(p0 - __bfloat162float(h0),
                                        p1 - __bfloat162float(h1));
            pa_lo[kk][o + 1] = pack_bf2(p2 - __bfloat162float(h2),
                                        p3 - __bfloat162float(h3));
        }
        sum0 += __shfl_xor_sync(0xffffffffu, sum0, 1);
        sum0 += __shfl_xor_sync(0xffffffffu, sum0, 2);
        sum1 += __shfl_xor_sync(0xffffffffu, sum1, 1);
        sum1 += __shfl_xor_sync(0xffffffffu, sum1, 2);
        l0 = l0 * c0 + sum0;
        l1 = l1 * c1 + sum1;
#pragma unroll
        for (int t = 0; t < 8; t++) {
            oacc[t][0] *= c0; oacc[t][1] *= c0;
            oacc[t][2] *= c1; oacc[t][3] *= c1;
        }

        // ---- O += P @ V (3 split passes) ----
#pragma unroll
        for (int pass = 0; pass < 3; pass++) {
            uint32_t vT = (pass == 1) ? (st + 24576) : (st + 16384);
            const uint32_t (*pa)[4] = (pass == 2) ? pa_lo : pa_hi;
#pragma unroll
            for (int kk = 0; kk < 4; kk++) {
                int colb = kk * 32 + ((lane >> 4) << 4);
#pragma unroll
                for (int dt = 0; dt < 4; dt++) {
                    uint32_t r0, r1, r2, r3;
                    int row = dt * 16 + (lane & 15);
                    ldsm_x4(r0, r1, r2, r3, vT + sw128(row * 128 + colb));
                    mma_bf16(oacc[2 * dt + 0], pa[kk][0], pa[kk][1], pa[kk][2],
                             pa[kk][3], r0, r2);
                    mma_bf16(oacc[2 * dt + 1], pa[kk][0], pa[kk][1], pa[kk][2],
                             pa[kk][3], r1, r3);
                }
            }
        }

        __syncthreads();
        if (kb + 2 < NIT) load_kv(kb + 2, s);
    }

    // ---- epilogue ----
    float inv0 = 1.0f / l0, inv1 = 1.0f / l1;
    int r_g0 = qb * 128 + wid * 16 + (lane >> 2);
#pragma unroll
    for (int t = 0; t < 8; t++) {
        int col = h * 64 + t * 8 + (lane & 3) * 2;
        float2 v0 = make_float2(oacc[t][0] * inv0, oacc[t][1] * inv0);
        float2 v1 = make_float2(oacc[t][2] * inv1, oacc[t][3] * inv1);
        *(float2*)&Out[((size_t)b * SS + r_g0) * DD + col] = v0;
        *(float2*)&Out[((size_t)b * SS + r_g0 + 8) * DD + col] = v1;
    }
}

extern "C" void kernel_launch(void* const* d_in, const int* in_sizes, int n_in,
                              void* d_out, int out_size) {
    const float* X = (const float*)d_in[0];     // [16,1024,1024]
    const float* W = (const float*)d_in[1];     // [2048,1024]
    const float* bias = (const float*)d_in[2];  // [2048]
    float* Out = (float*)d_out;                 // [16,1024,1024]

    cudaFuncSetAttribute(gemm_hmma, cudaFuncAttributeMaxDynamicSharedMemorySize,
                         GEMM_SMEM);
    cudaFuncSetAttribute(attn_tc, cudaFuncAttributeMaxDynamicSharedMemorySize,
                         ATT_SMEM);

    conv_x<<<(BB * SS * DD + 255) / 256, 256>>>(X);
    conv_w<<<(2048 * 1024 + 255) / 256, 256>>>(W);
    conv_vt<<<dim3(16, HH, BB), 256>>>(X);
    gemm_hmma<<<dim3(16, 128), 256, GEMM_SMEM>>>(bias);

    attn_tc<<<dim3(SS / 128, HH, BB), 256, ATT_SMEM>>>(Out);
}